// round 5
// baseline (speedup 1.0000x reference)
#include <cuda_runtime.h>
#include <cuda_fp16.h>
#include <mma.h>
#include <cstdint>
#include <math_constants.h>

using namespace nvcuda;

#define NODES 50000
#define D 128
#define C 40
#define CPAD 64
#define EDGES_MAX 1600000
#define SCAN_B 49          // 49 * 1024 = 50176 >= NODES
#define SCAN_PAD 50176

// ---------------- scratch (__device__ globals; no allocations) ----------------
__device__ __half g_S1h[NODES * D];     // x @ W1   (fp16)
__device__ __half g_Hh [NODES * D];     // relu(agg + b1) (fp16)
__device__ __half g_S2h[NODES * C];     // H @ W2   (fp16)
__device__ int    g_cnt[SCAN_PAD];      // zero-init at load; scanC re-zeros
__device__ int    g_scanA[SCAN_PAD];
__device__ int    g_bsum[64];
__device__ int    g_rs[NODES + 1];
__device__ int    g_cur[NODES];
__device__ int2   g_edge[EDGES_MAX];    // {col, weight-bits}, CSR order

// ================= CSR build =================
__global__ void hist_kernel(const int* __restrict__ ei, int E) {
    int e = blockIdx.x * blockDim.x + threadIdx.x;
    if (e < E) atomicAdd(&g_cnt[ei[e]], 1);
}

__global__ void scanA_kernel() {
    __shared__ int sh[1024];
    int t = threadIdx.x;
    int i = blockIdx.x * 1024 + t;
    sh[t] = g_cnt[i];
    __syncthreads();
#pragma unroll
    for (int off = 1; off < 1024; off <<= 1) {
        int add = (t >= off) ? sh[t - off] : 0;
        __syncthreads();
        sh[t] += add;
        __syncthreads();
    }
    g_scanA[i] = sh[t];
    if (t == 1023) g_bsum[blockIdx.x] = sh[1023];
}

// scanC: adds block offset, writes rs/cur, and RESETS g_cnt for the next call
__global__ void scanC_kernel() {
    __shared__ int s_off;
    __shared__ int warp_s[2];
    int t = threadIdx.x;
    if (t < 64) {
        int v = (t < (int)blockIdx.x) ? g_bsum[t] : 0;
#pragma unroll
        for (int off = 16; off > 0; off >>= 1)
            v += __shfl_down_sync(0xffffffffu, v, off);
        if ((t & 31) == 0) warp_s[t >> 5] = v;
    }
    __syncthreads();
    if (t == 0) s_off = warp_s[0] + warp_s[1];
    __syncthreads();
    int i = blockIdx.x * 1024 + t;
    int incl = g_scanA[i] + s_off;
    int cnt = g_cnt[i];
    g_cnt[i] = 0;                       // reset for next launch
    if (i < NODES) {
        int ex = incl - cnt;
        g_rs[i]  = ex;
        g_cur[i] = ex;
        if (i == NODES - 1) g_rs[NODES] = incl;
    }
}

__global__ void scatter_kernel(const int* __restrict__ ei,
                               const float* __restrict__ ew, int E) {
    int e = blockIdx.x * blockDim.x + threadIdx.x;
    if (e >= E) return;
    int r = ei[e];
    int p = atomicAdd(&g_cur[r], 1);
    g_edge[p] = make_int2(ei[E + e], __float_as_int(ew[e]));
}

// ================= GEMM1 (tensor cores): S1h = fp16(x) @ fp16(W1) =============
// block: 256 thr (8 warps), 64 rows. smem: xs half[64][128] + W1h half[128][128]
__global__ void gemm1_kernel(const float* __restrict__ x,
                             const float* __restrict__ W1, int n) {
    __shared__ __align__(16) char smem_raw[49152];
    __half* xs  = (__half*)smem_raw;                 // 16 KB
    __half* W1h = (__half*)(smem_raw + 16384);       // 32 KB
    float*  Sf  = (float*)smem_raw;                  // reused: 64x128 f32 = 32 KB

    int base = blockIdx.x * 64;
    int tid = threadIdx.x;

    // load + convert x tile (64x128) : 2048 float4, 8 per thread
    {
        const float4* xv = (const float4*)x;
        for (int i = tid; i < 64 * 32; i += 256) {
            int r = base + (i >> 5);
            float4 v = (r < n) ? xv[(long long)r * 32 + (i & 31)]
                               : make_float4(0, 0, 0, 0);
            __half2 h01 = __floats2half2_rn(v.x, v.y);
            __half2 h23 = __floats2half2_rn(v.z, v.w);
            uint2 pk;
            pk.x = *reinterpret_cast<unsigned*>(&h01);
            pk.y = *reinterpret_cast<unsigned*>(&h23);
            ((uint2*)xs)[i] = pk;
        }
    }
    // load + convert W1 (128x128)
    {
        const float4* Wv = (const float4*)W1;
        for (int i = tid; i < 128 * 32; i += 256) {
            float4 v = Wv[i];
            __half2 h01 = __floats2half2_rn(v.x, v.y);
            __half2 h23 = __floats2half2_rn(v.z, v.w);
            uint2 pk;
            pk.x = *reinterpret_cast<unsigned*>(&h01);
            pk.y = *reinterpret_cast<unsigned*>(&h23);
            ((uint2*)W1h)[i] = pk;
        }
    }
    __syncthreads();

    int wid = tid >> 5;
    int band = wid & 3;           // rows band*16..+15
    int ch   = wid >> 2;          // cols ch*64..+63
    wmma::fragment<wmma::accumulator, 16, 16, 16, float> acc[4];
#pragma unroll
    for (int c = 0; c < 4; c++) wmma::fill_fragment(acc[c], 0.0f);
#pragma unroll
    for (int k = 0; k < 8; k++) {
        wmma::fragment<wmma::matrix_a, 16, 16, 16, __half, wmma::row_major> a;
        wmma::load_matrix_sync(a, xs + (band * 16) * 128 + k * 16, 128);
#pragma unroll
        for (int c = 0; c < 4; c++) {
            wmma::fragment<wmma::matrix_b, 16, 16, 16, __half, wmma::row_major> b;
            wmma::load_matrix_sync(b, W1h + (k * 16) * 128 + ch * 64 + c * 16, 128);
            wmma::mma_sync(acc[c], a, b, acc[c]);
        }
    }
    __syncthreads();   // done reading xs/W1h; reuse as float out
#pragma unroll
    for (int c = 0; c < 4; c++)
        wmma::store_matrix_sync(Sf + (band * 16) * 128 + ch * 64 + c * 16,
                                acc[c], 128, wmma::mem_row_major);
    __syncthreads();
    // convert + write out (row-major linear copy)
    {
        __half2* outv = (__half2*)g_S1h;
        for (int i = tid; i < 64 * 64; i += 256) {   // half2 units
            int r = base + (i >> 6);
            if (r < n) {
                __half2 h = __floats2half2_rn(Sf[2 * i], Sf[2 * i + 1]);
                outv[(long long)base * 64 + i] = h;
            }
        }
    }
}

// ================= SpMM1 (gather fp16, warp/row) + bias + relu -> fp16 H ======
__device__ __forceinline__ void fma4h(float4& acc, float w, uint2 pk) {
    __half2 h01 = *reinterpret_cast<__half2*>(&pk.x);
    __half2 h23 = *reinterpret_cast<__half2*>(&pk.y);
    float2 f01 = __half22float2(h01);
    float2 f23 = __half22float2(h23);
    acc.x = fmaf(w, f01.x, acc.x); acc.y = fmaf(w, f01.y, acc.y);
    acc.z = fmaf(w, f23.x, acc.z); acc.w = fmaf(w, f23.y, acc.w);
}

__global__ void spmm1_kernel(const float* __restrict__ b1) {
    int w = (blockIdx.x * blockDim.x + threadIdx.x) >> 5;
    int lane = threadIdx.x & 31;
    if (w >= NODES) return;
    int i = g_rs[w], end = g_rs[w + 1];
    float4 acc = make_float4(0, 0, 0, 0);
    const uint2* S1v = (const uint2*)g_S1h;
    for (; i + 4 <= end; i += 4) {
        int2 e0 = g_edge[i], e1 = g_edge[i + 1], e2 = g_edge[i + 2], e3 = g_edge[i + 3];
        uint2 v0 = S1v[(long long)e0.x * 32 + lane];
        uint2 v1 = S1v[(long long)e1.x * 32 + lane];
        uint2 v2 = S1v[(long long)e2.x * 32 + lane];
        uint2 v3 = S1v[(long long)e3.x * 32 + lane];
        fma4h(acc, __int_as_float(e0.y), v0);
        fma4h(acc, __int_as_float(e1.y), v1);
        fma4h(acc, __int_as_float(e2.y), v2);
        fma4h(acc, __int_as_float(e3.y), v3);
    }
    for (; i < end; i++) {
        int2 e0 = g_edge[i];
        uint2 v0 = S1v[(long long)e0.x * 32 + lane];
        fma4h(acc, __int_as_float(e0.y), v0);
    }
    float4 bv = ((const float4*)b1)[lane];
    acc.x = fmaxf(acc.x + bv.x, 0.0f);
    acc.y = fmaxf(acc.y + bv.y, 0.0f);
    acc.z = fmaxf(acc.z + bv.z, 0.0f);
    acc.w = fmaxf(acc.w + bv.w, 0.0f);
    __half2 h01 = __floats2half2_rn(acc.x, acc.y);
    __half2 h23 = __floats2half2_rn(acc.z, acc.w);
    uint2 pk;
    pk.x = *reinterpret_cast<unsigned*>(&h01);
    pk.y = *reinterpret_cast<unsigned*>(&h23);
    ((uint2*)g_Hh)[(long long)w * 32 + lane] = pk;
}

// ================= GEMM2 (tensor cores): S2h = Hh @ fp16(W2 padded) ===========
// block: 256 thr (8 warps), 64 rows. smem: Hh half[64][128] + W2h half[128][64]
__global__ void gemm2_kernel(const float* __restrict__ W2, int n) {
    __shared__ __align__(16) char smem_raw[32768];
    __half* Hs  = (__half*)smem_raw;                 // 16 KB
    __half* W2h = (__half*)(smem_raw + 16384);       // 16 KB (padded to 64 cols)
    float*  Sf  = (float*)smem_raw;                  // reused: 64x64 f32 = 16 KB

    int base = blockIdx.x * 64;
    int tid = threadIdx.x;

    // load H tile (fp16 already): 64x128 halves = 1024 uint4
    {
        const uint4* Hv = (const uint4*)g_Hh;
        for (int i = tid; i < 64 * 16; i += 256) {
            int r = base + (i >> 4);
            uint4 v = (r < n) ? Hv[(long long)r * 16 + (i & 15)]
                              : make_uint4(0, 0, 0, 0);
            ((uint4*)Hs)[i] = v;
        }
    }
    // load + pad W2 (128x40 f32 -> 128x64 half)
    for (int i = tid; i < 128 * CPAD; i += 256) {
        int r = i >> 6, c = i & 63;
        W2h[i] = (c < C) ? __float2half_rn(W2[r * C + c]) : __half(0.0f);
    }
    __syncthreads();

    int wid = tid >> 5;
    int band = wid & 3;           // rows band*16
    int cp   = wid >> 2;          // cols cp*32..+31 (2 frags)
    wmma::fragment<wmma::accumulator, 16, 16, 16, float> acc[2];
#pragma unroll
    for (int c = 0; c < 2; c++) wmma::fill_fragment(acc[c], 0.0f);
#pragma unroll
    for (int k = 0; k < 8; k++) {
        wmma::fragment<wmma::matrix_a, 16, 16, 16, __half, wmma::row_major> a;
        wmma::load_matrix_sync(a, Hs + (band * 16) * 128 + k * 16, 128);
#pragma unroll
        for (int c = 0; c < 2; c++) {
            wmma::fragment<wmma::matrix_b, 16, 16, 16, __half, wmma::row_major> b;
            wmma::load_matrix_sync(b, W2h + (k * 16) * CPAD + cp * 32 + c * 16, CPAD);
            wmma::mma_sync(acc[c], a, b, acc[c]);
        }
    }
    __syncthreads();
#pragma unroll
    for (int c = 0; c < 2; c++)
        wmma::store_matrix_sync(Sf + (band * 16) * CPAD + cp * 32 + c * 16,
                                acc[c], CPAD, wmma::mem_row_major);
    __syncthreads();
    // write first 40 cols
    for (int i = tid; i < 64 * C; i += 256) {
        int r = i / C, c = i % C;
        int gr = base + r;
        if (gr < n)
            g_S2h[(long long)gr * C + c] = __float2half_rn(Sf[r * CPAD + c]);
    }
}

// ============ SpMM2 (gather fp16, 16 lanes/row) + b2 + log_softmax ============
__global__ void spmm2_kernel(const float* __restrict__ b2,
                             float* __restrict__ out) {
    int gt = blockIdx.x * blockDim.x + threadIdx.x;
    int r = gt >> 4;
    int lane16 = gt & 15;
    if (r >= NODES) return;
    bool act = lane16 < 10;
    int i = g_rs[r], end = g_rs[r + 1];
    float4 acc = make_float4(0, 0, 0, 0);
    const uint2* S2v = (const uint2*)g_S2h;   // row = 10 uint2
    for (; i + 2 <= end; i += 2) {
        int2 e0 = g_edge[i], e1 = g_edge[i + 1];
        if (act) {
            uint2 v0 = S2v[(long long)e0.x * 10 + lane16];
            uint2 v1 = S2v[(long long)e1.x * 10 + lane16];
            fma4h(acc, __int_as_float(e0.y), v0);
            fma4h(acc, __int_as_float(e1.y), v1);
        }
    }
    for (; i < end; i++) {
        int2 e0 = g_edge[i];
        if (act) {
            uint2 v0 = S2v[(long long)e0.x * 10 + lane16];
            fma4h(acc, __int_as_float(e0.y), v0);
        }
    }
    float4 v = make_float4(0, 0, 0, 0);
    if (act) {
        float4 bv = ((const float4*)b2)[lane16];
        v.x = acc.x + bv.x; v.y = acc.y + bv.y;
        v.z = acc.z + bv.z; v.w = acc.w + bv.w;
    }
    float m = act ? fmaxf(fmaxf(v.x, v.y), fmaxf(v.z, v.w)) : -CUDART_INF_F;
#pragma unroll
    for (int off = 8; off > 0; off >>= 1)
        m = fmaxf(m, __shfl_xor_sync(0xffffffffu, m, off, 16));
    float s = act ? (__expf(v.x - m) + __expf(v.y - m) +
                     __expf(v.z - m) + __expf(v.w - m)) : 0.0f;
#pragma unroll
    for (int off = 8; off > 0; off >>= 1)
        s += __shfl_xor_sync(0xffffffffu, s, off, 16);
    float lse = m + __logf(s);
    if (act) {
        float4 o;
        o.x = v.x - lse; o.y = v.y - lse; o.z = v.z - lse; o.w = v.w - lse;
        ((float4*)out)[(long long)r * 10 + lane16] = o;
    }
}

// =============================================================================
extern "C" void kernel_launch(void* const* d_in, const int* in_sizes, int n_in,
                              void* d_out, int out_size) {
    const float* x  = (const float*)d_in[0];
    const int*   ei = (const int*)d_in[1];    // int32
    const float* ew = (const float*)d_in[2];
    const float* W1 = (const float*)d_in[3];
    const float* b1 = (const float*)d_in[4];
    const float* W2 = (const float*)d_in[5];
    const float* b2 = (const float*)d_in[6];
    float* out = (float*)d_out;

    int n = in_sizes[0] / D;      // 50000
    int E = in_sizes[1] / 2;      // 1.6M

    // ---- CSR build (g_cnt is zero on entry; scanC re-zeros it) ----
    hist_kernel<<<(E + 255) / 256, 256>>>(ei, E);
    scanA_kernel<<<SCAN_B, 1024>>>();
    scanC_kernel<<<SCAN_B, 1024>>>();
    scatter_kernel<<<(E + 255) / 256, 256>>>(ei, ew, E);

    // ---- layer 1 ----
    gemm1_kernel<<<(n + 63) / 64, 256>>>(x, W1, n);
    {
        long long threads = (long long)n * 32;
        spmm1_kernel<<<(int)((threads + 255) / 256), 256>>>(b1);
    }

    // ---- layer 2 ----
    gemm2_kernel<<<(n + 63) / 64, 256>>>(W2, n);
    {
        long long threads = (long long)n * 16;
        spmm2_kernel<<<(int)((threads + 255) / 256), 256>>>(b2, out);
    }
}

// round 7
// speedup vs baseline: 1.4966x; 1.4966x over previous
#include <cuda_runtime.h>
#include <cuda_fp16.h>
#include <cstdint>
#include <math_constants.h>

#define NODES 50000
#define D 128
#define C 40
#define EDGES_MAX 1600000
#define SCAN_B 49          // 49 * 1024 = 50176 >= NODES
#define SCAN_PAD 50176

// ---------------- scratch (__device__ globals; no allocations) ----------------
__device__ __half g_S1h[NODES * D];     // x @ W1   (fp16 storage)
__device__ float  g_H [NODES * D];      // relu(agg + b1)  (fp32)
__device__ __half g_S2h[NODES * C];     // H @ W2   (fp16 storage)
__device__ int    g_cnt[SCAN_PAD];      // zero at load; scanC re-zeros each call
__device__ int    g_scanA[SCAN_PAD];
__device__ int    g_bsum[64];
__device__ int    g_rs[NODES + 1];
__device__ int    g_cur[NODES];
__device__ int2   g_edge[EDGES_MAX];    // {col, weight-bits}, CSR order

// ================= CSR build =================
__global__ void hist_kernel(const int* __restrict__ ei, int E) {
    int t = blockIdx.x * blockDim.x + threadIdx.x;
    int base = t * 4;
    if (base >= E) return;
    if (base + 4 <= E && (E & 3) == 0) {
        int4 r4 = *(const int4*)(ei + base);
        atomicAdd(&g_cnt[r4.x], 1);
        atomicAdd(&g_cnt[r4.y], 1);
        atomicAdd(&g_cnt[r4.z], 1);
        atomicAdd(&g_cnt[r4.w], 1);
    } else {
        for (int j = base; j < E && j < base + 4; j++)
            atomicAdd(&g_cnt[ei[j]], 1);
    }
}

__global__ void scanA_kernel() {
    __shared__ int sh[1024];
    int t = threadIdx.x;
    int i = blockIdx.x * 1024 + t;
    sh[t] = g_cnt[i];
    __syncthreads();
#pragma unroll
    for (int off = 1; off < 1024; off <<= 1) {
        int add = (t >= off) ? sh[t - off] : 0;
        __syncthreads();
        sh[t] += add;
        __syncthreads();
    }
    g_scanA[i] = sh[t];
    if (t == 1023) g_bsum[blockIdx.x] = sh[1023];
}

// scanC: block offset + rs/cur write + reset of g_cnt for next graph replay
__global__ void scanC_kernel() {
    __shared__ int s_off;
    __shared__ int warp_s[2];
    int t = threadIdx.x;
    if (t < 64) {
        int v = (t < (int)blockIdx.x) ? g_bsum[t] : 0;
#pragma unroll
        for (int off = 16; off > 0; off >>= 1)
            v += __shfl_down_sync(0xffffffffu, v, off);
        if ((t & 31) == 0) warp_s[t >> 5] = v;
    }
    __syncthreads();
    if (t == 0) s_off = warp_s[0] + warp_s[1];
    __syncthreads();
    int i = blockIdx.x * 1024 + t;
    int incl = g_scanA[i] + s_off;
    int cnt = g_cnt[i];
    g_cnt[i] = 0;
    if (i < NODES) {
        int ex = incl - cnt;
        g_rs[i]  = ex;
        g_cur[i] = ex;
        if (i == NODES - 1) g_rs[NODES] = incl;
    }
}

__global__ void scatter_kernel(const int* __restrict__ ei,
                               const float* __restrict__ ew, int E) {
    int t = blockIdx.x * blockDim.x + threadIdx.x;
    int base = t * 4;
    if (base >= E) return;
    if (base + 4 <= E && (E & 3) == 0) {
        int4   r4 = *(const int4*)(ei + base);
        int4   c4 = *(const int4*)(ei + E + base);
        float4 w4 = *(const float4*)(ew + base);
        int p0 = atomicAdd(&g_cur[r4.x], 1);
        int p1 = atomicAdd(&g_cur[r4.y], 1);
        int p2 = atomicAdd(&g_cur[r4.z], 1);
        int p3 = atomicAdd(&g_cur[r4.w], 1);
        g_edge[p0] = make_int2(c4.x, __float_as_int(w4.x));
        g_edge[p1] = make_int2(c4.y, __float_as_int(w4.y));
        g_edge[p2] = make_int2(c4.z, __float_as_int(w4.z));
        g_edge[p3] = make_int2(c4.w, __float_as_int(w4.w));
    } else {
        for (int j = base; j < E && j < base + 4; j++) {
            int p = atomicAdd(&g_cur[ei[j]], 1);
            g_edge[p] = make_int2(ei[E + j], __float_as_int(ew[j]));
        }
    }
}

// ================= GEMM1: S1h = x @ W1 (64 rows/block, 256 thr, k-block 4) ====
#define G1_ROWS 64
__global__ void gemm1_kernel(const float* __restrict__ x,
                             const float* __restrict__ W1, int n) {
    __shared__ float xs[G1_ROWS * D];    // 32 KB
    int base = blockIdx.x * G1_ROWS;
    int tid = threadIdx.x;
    const float4* xv = (const float4*)x;
    float4* xsv = (float4*)xs;
    for (int i = tid; i < G1_ROWS * 32; i += 256) {
        int r = base + (i >> 5);
        xsv[i] = (r < n) ? xv[(long long)r * 32 + (i & 31)] : make_float4(0, 0, 0, 0);
    }
    __syncthreads();
    int cg = tid & 31;     // float4 column group (cols 4cg..4cg+3)
    int rg = tid >> 5;     // rows rg*8 .. rg*8+7
    float4 acc[8];
#pragma unroll
    for (int j = 0; j < 8; j++) acc[j] = make_float4(0, 0, 0, 0);
    const float4* Wv = (const float4*)W1;
    for (int k0 = 0; k0 < D; k0 += 4) {
        float4 wv0 = Wv[(k0 + 0) * 32 + cg];
        float4 wv1 = Wv[(k0 + 1) * 32 + cg];
        float4 wv2 = Wv[(k0 + 2) * 32 + cg];
        float4 wv3 = Wv[(k0 + 3) * 32 + cg];
#pragma unroll
        for (int j = 0; j < 8; j++) {
            float4 xr = *(const float4*)(xs + (rg * 8 + j) * D + k0);
            acc[j].x = fmaf(xr.x, wv0.x, acc[j].x);
            acc[j].y = fmaf(xr.x, wv0.y, acc[j].y);
            acc[j].z = fmaf(xr.x, wv0.z, acc[j].z);
            acc[j].w = fmaf(xr.x, wv0.w, acc[j].w);
            acc[j].x = fmaf(xr.y, wv1.x, acc[j].x);
            acc[j].y = fmaf(xr.y, wv1.y, acc[j].y);
            acc[j].z = fmaf(xr.y, wv1.z, acc[j].z);
            acc[j].w = fmaf(xr.y, wv1.w, acc[j].w);
            acc[j].x = fmaf(xr.z, wv2.x, acc[j].x);
            acc[j].y = fmaf(xr.z, wv2.y, acc[j].y);
            acc[j].z = fmaf(xr.z, wv2.z, acc[j].z);
            acc[j].w = fmaf(xr.z, wv2.w, acc[j].w);
            acc[j].x = fmaf(xr.w, wv3.x, acc[j].x);
            acc[j].y = fmaf(xr.w, wv3.y, acc[j].y);
            acc[j].z = fmaf(xr.w, wv3.z, acc[j].z);
            acc[j].w = fmaf(xr.w, wv3.w, acc[j].w);
        }
    }
    uint2* S1v = (uint2*)g_S1h;
#pragma unroll
    for (int j = 0; j < 8; j++) {
        int r = base + rg * 8 + j;
        if (r < n) {
            __half2 h01 = __floats2half2_rn(acc[j].x, acc[j].y);
            __half2 h23 = __floats2half2_rn(acc[j].z, acc[j].w);
            uint2 pk;
            pk.x = *reinterpret_cast<unsigned*>(&h01);
            pk.y = *reinterpret_cast<unsigned*>(&h23);
            S1v[(long long)r * 32 + cg] = pk;
        }
    }
}

// ================= SpMM1 (gather fp16, warp/row, 8-deep MLP) + bias + relu ====
__device__ __forceinline__ void fma4h(float4& acc, float w, uint2 pk) {
    __half2 h01 = *reinterpret_cast<__half2*>(&pk.x);
    __half2 h23 = *reinterpret_cast<__half2*>(&pk.y);
    float2 f01 = __half22float2(h01);
    float2 f23 = __half22float2(h23);
    acc.x = fmaf(w, f01.x, acc.x); acc.y = fmaf(w, f01.y, acc.y);
    acc.z = fmaf(w, f23.x, acc.z); acc.w = fmaf(w, f23.y, acc.w);
}

__global__ void spmm1_kernel(const float* __restrict__ b1) {
    int w = (blockIdx.x * blockDim.x + threadIdx.x) >> 5;
    int lane = threadIdx.x & 31;
    if (w >= NODES) return;
    int i = g_rs[w], end = g_rs[w + 1];
    float4 acc = make_float4(0, 0, 0, 0);
    const uint2* S1v = (const uint2*)g_S1h;
    for (; i + 8 <= end; i += 8) {
        int2 e[8];
#pragma unroll
        for (int j = 0; j < 8; j++) e[j] = g_edge[i + j];
        uint2 v[8];
#pragma unroll
        for (int j = 0; j < 8; j++) v[j] = S1v[(long long)e[j].x * 32 + lane];
#pragma unroll
        for (int j = 0; j < 8; j++) fma4h(acc, __int_as_float(e[j].y), v[j]);
    }
    for (; i < end; i++) {
        int2 e0 = g_edge[i];
        uint2 v0 = S1v[(long long)e0.x * 32 + lane];
        fma4h(acc, __int_as_float(e0.y), v0);
    }
    float4 bv = ((const float4*)b1)[lane];
    acc.x = fmaxf(acc.x + bv.x, 0.0f);
    acc.y = fmaxf(acc.y + bv.y, 0.0f);
    acc.z = fmaxf(acc.z + bv.z, 0.0f);
    acc.w = fmaxf(acc.w + bv.w, 0.0f);
    ((float4*)g_H)[(long long)w * 32 + lane] = acc;
}

// ================= GEMM2: S2h = H @ W2 (32 rows/block, 160 thr) ===============
#define G2_ROWS 32
__global__ void gemm2_kernel(const float* __restrict__ W2, int n) {
    __shared__ float hs[G2_ROWS * D];    // 16 KB
    int base = blockIdx.x * G2_ROWS;
    int tid = threadIdx.x;                // 160
    float4* hsv = (float4*)hs;
    const float4* Hv = (const float4*)g_H;
    for (int i = tid; i < G2_ROWS * 32; i += 160) {
        int r = base + (i >> 5);
        hsv[i] = (r < n) ? Hv[(long long)r * 32 + (i & 31)] : make_float4(0, 0, 0, 0);
    }
    __syncthreads();
    int c = tid % C;
    int rg = tid / C;      // 0..3, rows rg*8..+7
    float acc[8];
#pragma unroll
    for (int j = 0; j < 8; j++) acc[j] = 0.0f;
#pragma unroll 4
    for (int k = 0; k < D; k++) {
        float wv = W2[k * C + c];
#pragma unroll
        for (int j = 0; j < 8; j++)
            acc[j] = fmaf(hs[(rg * 8 + j) * D + k], wv, acc[j]);
    }
#pragma unroll
    for (int j = 0; j < 8; j++) {
        int r = base + rg * 8 + j;
        if (r < n) g_S2h[(long long)r * C + c] = __float2half_rn(acc[j]);
    }
}

// ============ SpMM2 (gather fp16, 16 lanes/row, 4-deep MLP) + logsoftmax ======
__global__ void spmm2_kernel(const float* __restrict__ b2,
                             float* __restrict__ out) {
    int gt = blockIdx.x * blockDim.x + threadIdx.x;
    int r = gt >> 4;
    int lane16 = gt & 15;
    if (r >= NODES) return;
    bool act = lane16 < 10;              // 10 uint2 chunks (4 halves) cover C=40
    int i = g_rs[r], end = g_rs[r + 1];
    float4 acc = make_float4(0, 0, 0, 0);
    const uint2* S2v = (const uint2*)g_S2h;   // row stride = 10 uint2
    for (; i + 4 <= end; i += 4) {
        int2 e[4];
#pragma unroll
        for (int j = 0; j < 4; j++) e[j] = g_edge[i + j];
        if (act) {
            uint2 v[4];
#pragma unroll
            for (int j = 0; j < 4; j++) v[j] = S2v[(long long)e[j].x * 10 + lane16];
#pragma unroll
            for (int j = 0; j < 4; j++) fma4h(acc, __int_as_float(e[j].y), v[j]);
        }
    }
    for (; i < end; i++) {
        int2 e0 = g_edge[i];
        if (act) {
            uint2 v0 = S2v[(long long)e0.x * 10 + lane16];
            fma4h(acc, __int_as_float(e0.y), v0);
        }
    }
    float4 v = make_float4(0, 0, 0, 0);
    if (act) {
        float4 bv = ((const float4*)b2)[lane16];
        v.x = acc.x + bv.x; v.y = acc.y + bv.y;
        v.z = acc.z + bv.z; v.w = acc.w + bv.w;
    }
    float m = act ? fmaxf(fmaxf(v.x, v.y), fmaxf(v.z, v.w)) : -CUDART_INF_F;
#pragma unroll
    for (int off = 8; off > 0; off >>= 1)
        m = fmaxf(m, __shfl_xor_sync(0xffffffffu, m, off, 16));
    float s = act ? (__expf(v.x - m) + __expf(v.y - m) +
                     __expf(v.z - m) + __expf(v.w - m)) : 0.0f;
#pragma unroll
    for (int off = 8; off > 0; off >>= 1)
        s += __shfl_xor_sync(0xffffffffu, s, off, 16);
    float lse = m + __logf(s);
    if (act) {
        float4 o;
        o.x = v.x - lse; o.y = v.y - lse; o.z = v.z - lse; o.w = v.w - lse;
        ((float4*)out)[(long long)r * 10 + lane16] = o;
    }
}

// =============================================================================
extern "C" void kernel_launch(void* const* d_in, const int* in_sizes, int n_in,
                              void* d_out, int out_size) {
    const float* x  = (const float*)d_in[0];
    const int*   ei = (const int*)d_in[1];    // int32
    const float* ew = (const float*)d_in[2];
    const float* W1 = (const float*)d_in[3];
    const float* b1 = (const float*)d_in[4];
    const float* W2 = (const float*)d_in[5];
    const float* b2 = (const float*)d_in[6];
    float* out = (float*)d_out;

    int n = in_sizes[0] / D;      // 50000
    int E = in_sizes[1] / 2;      // 1.6M

    // ---- CSR build (g_cnt zero on entry; scanC re-zeros) ----
    int eThreads = (E + 3) / 4;
    hist_kernel<<<(eThreads + 255) / 256, 256>>>(ei, E);
    scanA_kernel<<<SCAN_B, 1024>>>();
    scanC_kernel<<<SCAN_B, 1024>>>();
    scatter_kernel<<<(eThreads + 255) / 256, 256>>>(ei, ew, E);

    // ---- layer 1 ----
    gemm1_kernel<<<(n + G1_ROWS - 1) / G1_ROWS, 256>>>(x, W1, n);
    {
        long long threads = (long long)n * 32;
        spmm1_kernel<<<(int)((threads + 255) / 256), 256>>>(b1);
    }

    // ---- layer 2 ----
    gemm2_kernel<<<(n + G2_ROWS - 1) / G2_ROWS, 160>>>(W2, n);
    {
        long long threads = (long long)n * 16;
        spmm2_kernel<<<(int)((threads + 255) / 256), 256>>>(b2, out);
    }
}